// round 11
// baseline (speedup 1.0000x reference)
#include <cuda_runtime.h>

// SpikeCNN fused: one block = one image, all 8 timesteps.
// R11 = R10 (warp-specialized pipeline, 1 barrier/step) with p1 in fp32:
//   kills ~180 F2F converts per B-thread-step; window load = 3x LDS.128
//   (48B lane stride -> conflict-free; verified bank tiling).

#define TH 1.0f
#define TSTEPS 8
#define NT 224
#define XPITCH 33          // xpadT: col*33 + row (col-major)
#define C1CP 30            // c1s: c*840 + col*30 + row (col-major)
#define P1P 12             // p1f: [ic][rh(36)][k(12)] floats (k 0..10 used)
#define P1SZ (3 * 36 * P1P)

__global__ __launch_bounds__(NT, 4)
void snn_kernel(const float* __restrict__ x,
                const float* __restrict__ w1, const float* __restrict__ b1,
                const float* __restrict__ w2, const float* __restrict__ b2,
                const float* __restrict__ wf, const float* __restrict__ bf,
                float* __restrict__ out, int nb)
{
    __shared__ __align__(16) float xpadT[32 * XPITCH];   // 4224 B
    __shared__ __align__(16) float c1s[3 * 28 * C1CP];   // 10080 B (col-major)
    __shared__ __align__(16) float p1f[2][P1SZ];         // 10368 B double-buffered
    __shared__ __align__(16) float w2d[6 * 3 * 5 * 8];   // 2880 B [oc][ic][di][8]
    __shared__ __align__(16) float s2P[2][6 * 196];      // 9408 B [oc][grp][4]

    const int tid  = threadIdx.x;
    const int warp = tid >> 5;              // 0..6
    const int lane = tid & 31;
    const int b    = blockIdx.x;

    // ---- init ----
    for (int i = tid; i < 32 * XPITCH; i += NT) xpadT[i] = 0.f;
    for (int i = tid; i < 2 * P1SZ; i += NT)    p1f[0][i] = 0.f;
    for (int i = tid; i < 720; i += NT)         w2d[i]   = 0.f;
    __syncthreads();
    for (int i = tid; i < 450; i += NT) {
        int g = i / 5, dj = i - 5 * g;      // g = (oc*3+ic)*5+di
        w2d[g * 8 + dj] = w2[i];
    }
    const float* xb = x + (size_t)b * 784;
    for (int i = tid; i < 784; i += NT) {
        int r = i / 28, c = i % 28;
        xpadT[(c + 2) * XPITCH + (r + 2)] = xb[i];
    }
    __syncthreads();

    // ---- conv1 (once): warps 0..5 ----
    if (warp < 6 && lane < 28) {
        int c = warp % 3, colbase = (warp / 3) * 14, row = lane;
        float wr[25];
        #pragma unroll
        for (int k = 0; k < 25; k++) wr[k] = __ldg(&w1[c * 25 + k]);
        float bias = __ldg(&b1[c]);
        float acc[14];
        #pragma unroll
        for (int j = 0; j < 14; j++) acc[j] = bias;
        #pragma unroll
        for (int di = 0; di < 5; di++) {
            float v[18];
            #pragma unroll
            for (int k = 0; k < 18; k++)
                v[k] = xpadT[(colbase + k) * XPITCH + row + di];
            #pragma unroll
            for (int j = 0; j < 14; j++)
                #pragma unroll
                for (int dj = 0; dj < 5; dj++)
                    acc[j] += v[j + dj] * wr[di * 5 + dj];
        }
        #pragma unroll
        for (int j = 0; j < 14; j++)
            c1s[c * 840 + (colbase + j) * C1CP + row] = acc[j];
    }
    __syncthreads();   // c1s complete before phaseA reads it

    // ---- persistent register state ----
    float mr[12];                           // mem1: 3 tasks x 4 cells (all 7 warps)
    #pragma unroll
    for (int i = 0; i < 12; i++) mr[i] = 0.f;
    float m2r[7];                           // mem2: warps 0..5, oc = warp
    #pragma unroll
    for (int j = 0; j < 7; j++) m2r[j] = 0.f;
    const bool bact = (warp < 6 && lane < 28);
    const float b2r = bact ? __ldg(&b2[warp]) : 0.f;
    // mem3/acc3: warp-6 registers (warp-uniform across its lanes)
    float m3[10], a3[10];
    #pragma unroll
    for (int r = 0; r < 10; r++) { m3[r] = 0.f; a3[r] = 0.f; }

    const int  pi   = lane % 14;            // phase-A pooled row
    const int  dpj  = lane / 14;            // 0/1
    const bool aact = (lane < 28);

    // Phase A: mem1 += c1, fire, 2x2 pool -> p1f[pb]
    auto phaseA = [&](int pb) {
        if (aact) {
            float* p1 = p1f[pb];
            #pragma unroll
            for (int i = 0; i < 3; i++) {
                int task = warp * 3 + i;                // 0..20
                int c    = task / 7;
                int pp   = task - 7 * c;
                int pj   = 2 * pp + dpj;
                int base = c * 840 + (2 * pj) * C1CP + 2 * pi;
                float2 ca = *reinterpret_cast<const float2*>(&c1s[base]);
                float2 cb = *reinterpret_cast<const float2*>(&c1s[base + C1CP]);
                float m0 = mr[i * 4 + 0] + ca.x;
                float m1 = mr[i * 4 + 1] + ca.y;
                float m2 = mr[i * 4 + 2] + cb.x;
                float m3v = mr[i * 4 + 3] + cb.y;
                float s0 = (m0 >= TH) ? TH : 0.f;
                float s1 = (m1 >= TH) ? TH : 0.f;
                float s2 = (m2 >= TH) ? TH : 0.f;
                float s3 = (m3v >= TH) ? TH : 0.f;
                mr[i * 4 + 0] = m0 - s0;
                mr[i * 4 + 1] = m1 - s1;
                mr[i * 4 + 2] = m2 - s2;
                mr[i * 4 + 3] = m3v - s3;
                float val = 0.25f * (s0 + s1 + s2 + s3);
                int cpad = pj + 2;                      // 2..15
                int rb   = c * 432 + (pi + 2) * 2 * P1P;
                if (cpad <= 10) p1[rb + cpad] = val;             // h=0 row
                if (cpad >= 7)  p1[rb + P1P + (cpad - 7)] = val; // h=1 row
            }
        }
    };

    // Phase D (warp 6): fc + mem3 fire for timestep td, reading s2P[td&1]
    auto phaseD = [&](int td) {
        const float* buf = s2P[td & 1];
        float pv[10];
        #pragma unroll
        for (int i = 0; i < 10; i++) {
            int k = lane + 32 * i;
            if (k < 294) {
                float4 q = *reinterpret_cast<const float4*>(&buf[k * 4]);
                pv[i] = 0.25f * (q.x + q.y + q.z + q.w);
            } else pv[i] = 0.f;
        }
        #pragma unroll
        for (int r = 0; r < 10; r++) {
            float part = 0.f;
            const float* wrow = wf + r * 294;
            #pragma unroll
            for (int i = 0; i < 10; i++) {
                int k = lane + 32 * i;
                if (k < 294) part += pv[i] * __ldg(&wrow[k]);
            }
            #pragma unroll
            for (int s = 16; s > 0; s >>= 1)
                part += __shfl_xor_sync(0xffffffffu, part, s);
            float m  = m3[r] + part + __ldg(&bf[r]);
            float sp = (m >= TH) ? TH : 0.f;
            m3[r] = m - sp;
            a3[r] += sp;
            if (lane == 0) {
                if (td == 3) out[(size_t)b * 10 + r] = a3[r] * 0.25f;
                if (td == 7) out[(size_t)nb * 10 + (size_t)b * 10 + r] = a3[r] * 0.125f;
            }
        }
    };

    phaseA(0);           // p1 for t=0
    __syncthreads();

    // ---- pipelined time loop: ONE barrier per timestep ----
    for (int t = 0; t < TSTEPS; t++) {
        if (warp < 6) {
            // B(t): conv2 + mem2 fire. reads p1f[t&1], writes s2P[t&1]
            if (lane < 28) {
                const float* p1 = p1f[t & 1];
                const int oc  = warp;
                const int row = lane >> 1, h = lane & 1;
                float acc[7];
                #pragma unroll
                for (int j = 0; j < 7; j++) acc[j] = b2r;
                #pragma unroll
                for (int ic = 0; ic < 3; ic++) {
                    #pragma unroll
                    for (int di = 0; di < 5; di++) {
                        const float4* src = reinterpret_cast<const float4*>(
                            &p1[ic * 432 + (lane + 2 * di) * P1P]);
                        float4 A0 = src[0], A1 = src[1], A2 = src[2];
                        float v[11] = {A0.x, A0.y, A0.z, A0.w,
                                       A1.x, A1.y, A1.z, A1.w,
                                       A2.x, A2.y, A2.z};
                        const float* wp = &w2d[((oc * 3 + ic) * 5 + di) * 8];
                        float4 w4 = *reinterpret_cast<const float4*>(wp);
                        float  w5 = wp[4];
                        float wrow[5] = {w4.x, w4.y, w4.z, w4.w, w5};
                        #pragma unroll
                        for (int j = 0; j < 7; j++)
                            #pragma unroll
                            for (int dj = 0; dj < 5; dj++)
                                acc[j] += v[j + dj] * wrow[dj];
                    }
                }
                // fire + store pool-group-contiguous into s2P[t&1]
                float* sdst = s2P[t & 1];
                const int sbase = oc * 196 + (row >> 1) * 28 + (row & 1) * 2;
                #pragma unroll
                for (int j = 0; j < 7; j++) {
                    float m  = m2r[j] + acc[j];
                    float sp = (m >= TH) ? TH : 0.f;
                    m2r[j]   = m - sp;
                    int cc   = j + 7 * h;
                    sdst[sbase + (cc >> 1) * 4 + (cc & 1)] = sp;
                }
            }
            if (t < TSTEPS - 1) phaseA((t + 1) & 1);
        } else {
            // warp 6: D for previous timestep, then its A share
            if (t > 0) phaseD(t - 1);
            if (t < TSTEPS - 1) phaseA((t + 1) & 1);
        }
        __syncthreads();
    }
    // epilogue: D for the last timestep
    if (warp == 6) phaseD(TSTEPS - 1);
}

extern "C" void kernel_launch(void* const* d_in, const int* in_sizes, int n_in,
                              void* d_out, int out_size)
{
    const float* x  = (const float*)d_in[0];
    const float* w1 = (const float*)d_in[1];
    const float* b1 = (const float*)d_in[2];
    const float* w2 = (const float*)d_in[3];
    const float* b2 = (const float*)d_in[4];
    const float* wf = (const float*)d_in[5];
    const float* bf = (const float*)d_in[6];
    float* out = (float*)d_out;

    int nb = in_sizes[0] / 784;   // 4096
    snn_kernel<<<nb, NT>>>(x, w1, b1, w2, b2, wf, bf, out, nb);
}

// round 12
// speedup vs baseline: 1.1756x; 1.1756x over previous
#include <cuda_runtime.h>

// SpikeCNN fused: one block = one image, all 8 timesteps, warp-specialized.
// R12: conv2 via fma.rn.f32x2 with ZERO packing overhead:
//   outputs paired (cc, cc+7) within one oc; p1 stored as float2(P[k],P[k+7])
//   so every packed operand is a natural LDS.128/LDS.64; weights stored (w,w).
//   Warps 0-2: conv2 (oc-pair per warp). Warp 3: fc/mem3 (pipelined, t-1).
//   Warps 4-6: phase A (one channel each, mem1 in regs). 1 barrier/step.
//   Bitwise-identical accumulation order vs scalar reference.

#define TH 1.0f
#define TSTEPS 8
#define NT 224
#define XPITCH 33           // xpadT: col*33 + row (col-major)
#define C1CP 30             // c1s: c*840 + col*30 + row (col-major)
#define P1K 14              // k slots per row (k 0..10 used; pitch 14 float2 = 112B)
#define P1ROWS 18           // padded pooled rows
#define P1SZ (3 * P1ROWS * P1K)   // float2 elements per buffer

__device__ __forceinline__ unsigned long long pk2(float lo, float hi) {
    unsigned long long r;
    asm("mov.b64 %0, {%1,%2};" : "=l"(r) : "f"(lo), "f"(hi));
    return r;
}
__device__ __forceinline__ void fma2(unsigned long long& acc,
                                     unsigned long long a, unsigned long long b) {
    asm("fma.rn.f32x2 %0, %1, %2, %0;" : "+l"(acc) : "l"(a), "l"(b));
}
__device__ __forceinline__ float2 upk(unsigned long long v) {
    float2 r;
    asm("mov.b64 {%0,%1}, %2;" : "=f"(r.x), "=f"(r.y) : "l"(v));
    return r;
}

__global__ __launch_bounds__(NT, 4)
void snn_kernel(const float* __restrict__ x,
                const float* __restrict__ w1, const float* __restrict__ b1,
                const float* __restrict__ w2, const float* __restrict__ b2,
                const float* __restrict__ wf, const float* __restrict__ bf,
                float* __restrict__ out, int nb)
{
    __shared__ __align__(16) float  xpadT[32 * XPITCH];   // 4224 B
    __shared__ __align__(16) float  c1s[3 * 28 * C1CP];   // 10080 B (col-major)
    __shared__ __align__(16) float2 p1p[2][P1SZ];         // 12096 B, double-buffered
    __shared__ __align__(16) float2 w2q[90 * 6];          // (w,w) rows, pitch 6 -> 4320 B
    __shared__ __align__(16) float  s2P[2][6 * 196];      // 9408 B [oc][grp][4]

    const int tid  = threadIdx.x;
    const int warp = tid >> 5;              // 0..6
    const int lane = tid & 31;
    const int b    = blockIdx.x;

    // ---- init ----
    for (int i = tid; i < 32 * XPITCH; i += NT) xpadT[i] = 0.f;
    for (int i = tid; i < 2 * P1SZ; i += NT)    p1p[0][i] = make_float2(0.f, 0.f);
    for (int i = tid; i < 90 * 6; i += NT)      w2q[i]   = make_float2(0.f, 0.f);
    __syncthreads();
    // w2 flat: i = g*5 + dj with g = (oc*3+ic)*5+di
    for (int i = tid; i < 450; i += NT) {
        int g = i / 5, dj = i - 5 * g;
        float w = w2[i];
        w2q[g * 6 + dj] = make_float2(w, w);
    }
    const float* xb = x + (size_t)b * 784;
    for (int i = tid; i < 784; i += NT) {
        int r = i / 28, c = i % 28;
        xpadT[(c + 2) * XPITCH + (r + 2)] = xb[i];
    }
    __syncthreads();

    // ---- conv1 (once): warps 0..5 ----
    if (warp < 6 && lane < 28) {
        int c = warp % 3, colbase = (warp / 3) * 14, row = lane;
        float wr[25];
        #pragma unroll
        for (int k = 0; k < 25; k++) wr[k] = __ldg(&w1[c * 25 + k]);
        float bias = __ldg(&b1[c]);
        float acc[14];
        #pragma unroll
        for (int j = 0; j < 14; j++) acc[j] = bias;
        #pragma unroll
        for (int di = 0; di < 5; di++) {
            float v[18];
            #pragma unroll
            for (int k = 0; k < 18; k++)
                v[k] = xpadT[(colbase + k) * XPITCH + row + di];
            #pragma unroll
            for (int j = 0; j < 14; j++)
                #pragma unroll
                for (int dj = 0; dj < 5; dj++)
                    acc[j] += v[j + dj] * wr[di * 5 + dj];
        }
        #pragma unroll
        for (int j = 0; j < 14; j++)
            c1s[c * 840 + (colbase + j) * C1CP + row] = acc[j];
    }
    __syncthreads();   // c1s complete before phase A reads it

    // ---- persistent register state ----
    // B warps (0..2): oc = 2*warp + (lane&1), row = lane>>1 (lane<28)
    const bool bwarp = (warp < 3);
    const bool bact  = bwarp && (lane < 28);
    const int  boc   = 2 * warp + (lane & 1);
    const int  brow  = lane >> 1;
    float m2v[14];
    #pragma unroll
    for (int j = 0; j < 14; j++) m2v[j] = 0.f;
    const float b2r = bact ? __ldg(&b2[boc]) : 0.f;
    // A warps (4..6): channel c = warp-4, 7 tasks, mem1 in regs
    const bool awarp = (warp >= 4);
    const int  ach   = warp - 4;
    float mr[28];
    #pragma unroll
    for (int i = 0; i < 28; i++) mr[i] = 0.f;
    const int  pi  = lane % 14;
    const int  dpj = lane / 14;
    const bool aact = awarp && (lane < 28);
    // D warp (3): mem3/acc3 regs
    float m3[10], a3[10];
    #pragma unroll
    for (int r = 0; r < 10; r++) { m3[r] = 0.f; a3[r] = 0.f; }

    // Phase A: mem1 += c1, fire, 2x2 pool -> p1p[pb] paired layout
    auto phaseA = [&](int pb) {
        if (aact) {
            float* p1f = reinterpret_cast<float*>(p1p[pb]);
            #pragma unroll
            for (int i = 0; i < 7; i++) {
                int pj   = 2 * i + dpj;                 // pooled col 0..13
                int base = ach * 840 + (2 * pj) * C1CP + 2 * pi;
                float2 ca = *reinterpret_cast<const float2*>(&c1s[base]);
                float2 cb = *reinterpret_cast<const float2*>(&c1s[base + C1CP]);
                float m0 = mr[i * 4 + 0] + ca.x;
                float m1 = mr[i * 4 + 1] + ca.y;
                float m2 = mr[i * 4 + 2] + cb.x;
                float m3v = mr[i * 4 + 3] + cb.y;
                float s0 = (m0 >= TH) ? TH : 0.f;
                float s1 = (m1 >= TH) ? TH : 0.f;
                float s2 = (m2 >= TH) ? TH : 0.f;
                float s3 = (m3v >= TH) ? TH : 0.f;
                mr[i * 4 + 0] = m0 - s0;
                mr[i * 4 + 1] = m1 - s1;
                mr[i * 4 + 2] = m2 - s2;
                mr[i * 4 + 3] = m3v - s3;
                float val = 0.25f * (s0 + s1 + s2 + s3);
                int padcol = pj + 2;                    // 2..15
                int rbase  = (ach * P1ROWS + (pi + 2)) * P1K;
                if (padcol <= 13) p1f[(rbase + padcol) * 2]         = val;  // .x
                if (padcol >= 7)  p1f[(rbase + padcol - 7) * 2 + 1] = val;  // .y
            }
        }
    };

    // Phase D (warp 3): fc + mem3 fire for timestep td
    auto phaseD = [&](int td) {
        const float* buf = s2P[td & 1];
        float pv[10];
        #pragma unroll
        for (int i = 0; i < 10; i++) {
            int k = lane + 32 * i;
            if (k < 294) {
                float4 q = *reinterpret_cast<const float4*>(&buf[k * 4]);
                pv[i] = 0.25f * (q.x + q.y + q.z + q.w);
            } else pv[i] = 0.f;
        }
        #pragma unroll
        for (int r = 0; r < 10; r++) {
            float part = 0.f;
            const float* wrow = wf + r * 294;
            #pragma unroll
            for (int i = 0; i < 10; i++) {
                int k = lane + 32 * i;
                if (k < 294) part += pv[i] * __ldg(&wrow[k]);
            }
            #pragma unroll
            for (int s = 16; s > 0; s >>= 1)
                part += __shfl_xor_sync(0xffffffffu, part, s);
            float m  = m3[r] + part + __ldg(&bf[r]);
            float sp = (m >= TH) ? TH : 0.f;
            m3[r] = m - sp;
            a3[r] += sp;
            if (lane == 0) {
                if (td == 3) out[(size_t)b * 10 + r] = a3[r] * 0.25f;
                if (td == 7) out[(size_t)nb * 10 + (size_t)b * 10 + r] = a3[r] * 0.125f;
            }
        }
    };

    phaseA(0);           // p1 for t=0 (warps 4-6)
    __syncthreads();

    // ---- pipelined time loop: ONE barrier per timestep ----
    for (int t = 0; t < TSTEPS; t++) {
        if (bwarp) {
            // B(t): conv2 via FFMA2. reads p1p[t&1], writes s2P[t&1]
            if (lane < 28) {
                const float2* p1 = p1p[t & 1];
                unsigned long long A2[7];
                unsigned long long bini = pk2(b2r, b2r);
                #pragma unroll
                for (int j = 0; j < 7; j++) A2[j] = bini;
                #pragma unroll
                for (int ic = 0; ic < 3; ic++) {
                    #pragma unroll
                    for (int di = 0; di < 5; di++) {
                        const float2* src = &p1[(ic * P1ROWS + brow + di) * P1K];
                        ulonglong2 u0 = *reinterpret_cast<const ulonglong2*>(src);
                        ulonglong2 u1 = *reinterpret_cast<const ulonglong2*>(src + 2);
                        ulonglong2 u2 = *reinterpret_cast<const ulonglong2*>(src + 4);
                        ulonglong2 u3 = *reinterpret_cast<const ulonglong2*>(src + 6);
                        ulonglong2 u4 = *reinterpret_cast<const ulonglong2*>(src + 8);
                        unsigned long long pv10 =
                            *reinterpret_cast<const unsigned long long*>(src + 10);
                        unsigned long long pv[11] = {u0.x, u0.y, u1.x, u1.y, u2.x,
                                                     u2.y, u3.x, u3.y, u4.x, u4.y, pv10};
                        const int g = (boc * 3 + ic) * 5 + di;
                        const float2* wp = &w2q[g * 6];
                        ulonglong2 wA = *reinterpret_cast<const ulonglong2*>(wp);
                        ulonglong2 wB = *reinterpret_cast<const ulonglong2*>(wp + 2);
                        unsigned long long w4v =
                            *reinterpret_cast<const unsigned long long*>(wp + 4);
                        unsigned long long wv[5] = {wA.x, wA.y, wB.x, wB.y, w4v};
                        #pragma unroll
                        for (int dj = 0; dj < 5; dj++)
                            #pragma unroll
                            for (int j = 0; j < 7; j++)
                                fma2(A2[j], pv[j + dj], wv[dj]);
                    }
                }
                // fire + store pool-group layout: out (boc, brow, cc) and (.., cc+7)
                float* sdst = s2P[t & 1];
                const int obase = boc * 196;
                #pragma unroll
                for (int j = 0; j < 7; j++) {
                    float2 q = upk(A2[j]);
                    // cc = j
                    {
                        float m  = m2v[j] + q.x;
                        float sp = (m >= TH) ? TH : 0.f;
                        m2v[j]   = m - sp;
                        int cc = j;
                        sdst[obase + ((brow >> 1) * 7 + (cc >> 1)) * 4 +
                             (brow & 1) * 2 + (cc & 1)] = sp;
                    }
                    // cc = j + 7
                    {
                        float m  = m2v[j + 7] + q.y;
                        float sp = (m >= TH) ? TH : 0.f;
                        m2v[j + 7] = m - sp;
                        int cc = j + 7;
                        sdst[obase + ((brow >> 1) * 7 + (cc >> 1)) * 4 +
                             (brow & 1) * 2 + (cc & 1)] = sp;
                    }
                }
            }
        } else if (warp == 3) {
            if (t > 0) phaseD(t - 1);
        } else {
            if (t < TSTEPS - 1) phaseA((t + 1) & 1);
        }
        __syncthreads();
    }
    // epilogue: D for the last timestep
    if (warp == 3) phaseD(TSTEPS - 1);
}

extern "C" void kernel_launch(void* const* d_in, const int* in_sizes, int n_in,
                              void* d_out, int out_size)
{
    const float* x  = (const float*)d_in[0];
    const float* w1 = (const float*)d_in[1];
    const float* b1 = (const float*)d_in[2];
    const float* w2 = (const float*)d_in[3];
    const float* b2 = (const float*)d_in[4];
    const float* wf = (const float*)d_in[5];
    const float* bf = (const float*)d_in[6];
    float* out = (float*)d_out;

    int nb = in_sizes[0] / 784;   // 4096
    snn_kernel<<<nb, NT>>>(x, w1, b1, w2, b2, wf, bf, out, nb);
}